// round 1
// baseline (speedup 1.0000x reference)
#include <cuda_runtime.h>
#include <math.h>

// ---------------------------------------------------------------------------
// HEPOS cross attention, fp32 baseline.
// B=4, T=1024, S=4096, D=1024, 16 heads x 64, head strides [1,2,4,8]*4.
//
// Pipeline (5 kernels, one stream, graph-capturable):
//   1. Q = dec @ Wq^T + bq                      (SGEMM-NT, 4096x1024x1024)
//   2. Kc = strided-rows(enc) @ Wk_cols^T + bk  (per stride-group, compact)
//   3. Vc = same for V
//   4. flash attention per (b, head, 64-query tile) -> A (B,T,1024)
//   5. out = A @ Wo^T + bo
//
// K/V compaction: stride group g in {0..3} has stride 2^g and heads
// {g, g+4, g+8, g+12}. Region layout: [g][b][m][256] where column
// n = hInGroup*64 + d, row m is encoder row m*2^g.
// ---------------------------------------------------------------------------

#define BATCH 4
#define TLEN 1024
#define SLEN 4096
#define DMODEL 1024

// Scratch (static __device__ — no allocation in kernel_launch).
__device__ float g_Q[(size_t)BATCH * TLEN * DMODEL];      // 16 MB
__device__ float g_Kc[7864320];                            // 31.5 MB
__device__ float g_Vc[7864320];                            // 31.5 MB
__device__ float g_A[(size_t)BATCH * TLEN * DMODEL];       // 16 MB

__device__ __host__ __forceinline__ size_t grp_off(int g) {
    // float offsets of group regions: sizes 4*Sg*256 for Sg = 4096>>g
    size_t off = 0;
    if (g > 0) off += 4194304u;   // g0: 4*4096*256
    if (g > 1) off += 2097152u;   // g1: 4*2048*256
    if (g > 2) off += 1048576u;   // g2: 4*1024*256
    return off;
}

// ---------------------------------------------------------------------------
// Generic SGEMM-NT with bias:  C[M,N] = A[M,K] @ W[N,K]^T + bias[N]
// 128x128 block tile, BK=8, 256 threads, 8x8 micro-tile per thread.
// Requires M,N % 128 == 0, K % 8 == 0.
// ---------------------------------------------------------------------------
__global__ __launch_bounds__(256) void hepos_sgemm_nt_bias(
    const float* __restrict__ A, const float* __restrict__ W,
    const float* __restrict__ bias, float* __restrict__ C,
    int M, int N, int K)
{
    __shared__ float As[8][128];
    __shared__ float Bs[8][128];
    const int tid = threadIdx.x;
    const int tx = tid & 15, ty = tid >> 4;
    const int m0 = blockIdx.y * 128, n0 = blockIdx.x * 128;
    const int lrow = tid >> 1;
    const int lk4 = (tid & 1) * 4;

    const float* Ap = A + (size_t)(m0 + lrow) * K + lk4;
    const float* Wp = W + (size_t)(n0 + lrow) * K + lk4;

    float acc[8][8];
#pragma unroll
    for (int i = 0; i < 8; i++)
#pragma unroll
        for (int j = 0; j < 8; j++) acc[i][j] = 0.f;

    for (int k0 = 0; k0 < K; k0 += 8) {
        float4 av = *(const float4*)(Ap + k0);
        float4 wv = *(const float4*)(Wp + k0);
        As[lk4 + 0][lrow] = av.x; As[lk4 + 1][lrow] = av.y;
        As[lk4 + 2][lrow] = av.z; As[lk4 + 3][lrow] = av.w;
        Bs[lk4 + 0][lrow] = wv.x; Bs[lk4 + 1][lrow] = wv.y;
        Bs[lk4 + 2][lrow] = wv.z; Bs[lk4 + 3][lrow] = wv.w;
        __syncthreads();
#pragma unroll
        for (int k = 0; k < 8; k++) {
            float4 a0 = *(const float4*)&As[k][ty * 4];
            float4 a1 = *(const float4*)&As[k][64 + ty * 4];
            float4 b0 = *(const float4*)&Bs[k][tx * 4];
            float4 b1 = *(const float4*)&Bs[k][64 + tx * 4];
            float ar[8] = {a0.x, a0.y, a0.z, a0.w, a1.x, a1.y, a1.z, a1.w};
            float br[8] = {b0.x, b0.y, b0.z, b0.w, b1.x, b1.y, b1.z, b1.w};
#pragma unroll
            for (int i = 0; i < 8; i++)
#pragma unroll
                for (int j = 0; j < 8; j++)
                    acc[i][j] = fmaf(ar[i], br[j], acc[i][j]);
        }
        __syncthreads();
    }

#pragma unroll
    for (int rr = 0; rr < 2; rr++)
#pragma unroll
        for (int r = 0; r < 4; r++) {
            int m = m0 + rr * 64 + ty * 4 + r;
#pragma unroll
            for (int cc = 0; cc < 2; cc++) {
                int n = n0 + cc * 64 + tx * 4;
                float4 bv = *(const float4*)(bias + n);
                float4 o;
                o.x = acc[rr * 4 + r][cc * 4 + 0] + bv.x;
                o.y = acc[rr * 4 + r][cc * 4 + 1] + bv.y;
                o.z = acc[rr * 4 + r][cc * 4 + 2] + bv.z;
                o.w = acc[rr * 4 + r][cc * 4 + 3] + bv.w;
                *(float4*)(C + (size_t)m * N + n) = o;
            }
        }
}

// ---------------------------------------------------------------------------
// Strided K/V projection per stride-group.
//   out[g][b][m][n] = sum_k enc[b][m*2^g][k] * W[wrow(n)][k] + bias[wrow(n)]
//   wrow(n) = (g + (n>>6)*4)*64 + (n & 63),  n in [0,256)
// Grid: x = n-tile (2), y = m-tile (up to 32, early-exit), z = g*4 + b.
// ---------------------------------------------------------------------------
__global__ __launch_bounds__(256) void hepos_kv_gemm(
    const float* __restrict__ enc, const float* __restrict__ W,
    const float* __restrict__ bias, float* __restrict__ out)
{
    const int z = blockIdx.z;
    const int g = z >> 2;
    const int b = z & 3;
    const int Mg = SLEN >> g;
    const int m0 = blockIdx.y * 128;
    if (m0 >= Mg) return;
    const int stride = 1 << g;
    const int n0 = blockIdx.x * 128;

    __shared__ float As[8][128];
    __shared__ float Bs[8][128];
    const int tid = threadIdx.x;
    const int tx = tid & 15, ty = tid >> 4;
    const int lrow = tid >> 1;
    const int lk4 = (tid & 1) * 4;

    const int ncol = n0 + lrow;
    const int hid = g + ((ncol >> 6) << 2);
    const int wrow = hid * 64 + (ncol & 63);

    const float* Ap = enc + ((size_t)b * SLEN + (size_t)(m0 + lrow) * stride) * DMODEL + lk4;
    const float* Wp = W + (size_t)wrow * DMODEL + lk4;

    float acc[8][8];
#pragma unroll
    for (int i = 0; i < 8; i++)
#pragma unroll
        for (int j = 0; j < 8; j++) acc[i][j] = 0.f;

    for (int k0 = 0; k0 < DMODEL; k0 += 8) {
        float4 av = *(const float4*)(Ap + k0);
        float4 wv = *(const float4*)(Wp + k0);
        As[lk4 + 0][lrow] = av.x; As[lk4 + 1][lrow] = av.y;
        As[lk4 + 2][lrow] = av.z; As[lk4 + 3][lrow] = av.w;
        Bs[lk4 + 0][lrow] = wv.x; Bs[lk4 + 1][lrow] = wv.y;
        Bs[lk4 + 2][lrow] = wv.z; Bs[lk4 + 3][lrow] = wv.w;
        __syncthreads();
#pragma unroll
        for (int k = 0; k < 8; k++) {
            float4 a0 = *(const float4*)&As[k][ty * 4];
            float4 a1 = *(const float4*)&As[k][64 + ty * 4];
            float4 b0 = *(const float4*)&Bs[k][tx * 4];
            float4 b1 = *(const float4*)&Bs[k][64 + tx * 4];
            float ar[8] = {a0.x, a0.y, a0.z, a0.w, a1.x, a1.y, a1.z, a1.w};
            float br[8] = {b0.x, b0.y, b0.z, b0.w, b1.x, b1.y, b1.z, b1.w};
#pragma unroll
            for (int i = 0; i < 8; i++)
#pragma unroll
                for (int j = 0; j < 8; j++)
                    acc[i][j] = fmaf(ar[i], br[j], acc[i][j]);
        }
        __syncthreads();
    }

    const size_t base = grp_off(g) + (size_t)b * Mg * 256;
#pragma unroll
    for (int rr = 0; rr < 2; rr++)
#pragma unroll
        for (int r = 0; r < 4; r++) {
            int m = m0 + rr * 64 + ty * 4 + r;
#pragma unroll
            for (int cc = 0; cc < 2; cc++) {
                int n = n0 + cc * 64 + tx * 4;
                int h2 = g + ((n >> 6) << 2);
                float4 bv = *(const float4*)(bias + h2 * 64 + (n & 63));
                float4 o;
                o.x = acc[rr * 4 + r][cc * 4 + 0] + bv.x;
                o.y = acc[rr * 4 + r][cc * 4 + 1] + bv.y;
                o.z = acc[rr * 4 + r][cc * 4 + 2] + bv.z;
                o.w = acc[rr * 4 + r][cc * 4 + 3] + bv.w;
                *(float4*)(out + base + (size_t)m * 256 + n) = o;
            }
        }
}

// ---------------------------------------------------------------------------
// Flash attention over compacted K/V.
// Block = (q-tile 64 rows) x (head) x (batch). 256 threads (16x16), each
// owns a 4x4 micro-tile of the 64x64 score tile and a 4x4 of the O tile.
// Smem (dynamic): Qt[64][68] (Q^T), Kt[64][68] (K^T), Pt[64][68] (S^T -> P^T),
//                 Vs[64][68] (V natural), sred[64].
// Online softmax: threads 0..63 own row stats m_i, l_i.
// ---------------------------------------------------------------------------
#define ATT_LD 68
#define ATT_SMEM ((4 * 64 * ATT_LD + 64) * sizeof(float))

__global__ __launch_bounds__(256) void hepos_attn(
    const float* __restrict__ Q, const float* __restrict__ K,
    const float* __restrict__ V, float* __restrict__ O)
{
    extern __shared__ float sm[];
    float* Qt = sm;                        // [d][i], 64x68
    float* Kt = Qt + 64 * ATT_LD;          // [d][j]
    float* Pt = Kt + 64 * ATT_LD;          // [j][i]
    float* Vs = Pt + 64 * ATT_LD;          // [j][d]
    float* sred = Vs + 64 * ATT_LD;        // alpha / 1/l

    const int t = threadIdx.x;
    const int tx = t & 15, ty = t >> 4;
    const int qt = blockIdx.x;
    // heavy heads (stride 1) first for load balance: y -> h
    const int y = blockIdx.y;
    const int h = ((y & 3) << 2) | (y >> 2);
    const int b = blockIdx.z;

    const int g = h & 3;
    const int hig = h >> 2;
    const int Sg = SLEN >> g;
    const float* Kb = K + grp_off(g) + (size_t)b * Sg * 256 + hig * 64;
    const float* Vb = V + grp_off(g) + (size_t)b * Sg * 256 + hig * 64;

    const int t0 = qt * 64;

    // load Q tile transposed: Qt[d][i] = Q[b, t0+i, h*64+d]
#pragma unroll
    for (int c = 0; c < 4; c++) {
        int idx = t + c * 256;
        int i = idx >> 4;
        int d4 = (idx & 15) * 4;
        float4 q = *(const float4*)(Q + ((size_t)(b * TLEN + t0 + i)) * DMODEL + h * 64 + d4);
        Qt[(d4 + 0) * ATT_LD + i] = q.x;
        Qt[(d4 + 1) * ATT_LD + i] = q.y;
        Qt[(d4 + 2) * ATT_LD + i] = q.z;
        Qt[(d4 + 3) * ATT_LD + i] = q.w;
    }

    float m_i = -INFINITY, l_i = 0.f;   // valid in threads t < 64 (row t)
    float o[4][4];
#pragma unroll
    for (int r = 0; r < 4; r++)
#pragma unroll
        for (int c = 0; c < 4; c++) o[r][c] = 0.f;

    const float scale = 0.125f;  // 1/sqrt(64)
    const int nch = Sg >> 6;

    for (int ch = 0; ch < nch; ch++) {
        __syncthreads();   // prior iteration's reads of Kt/Vs/Pt done
        const int jb = ch * 64;
        // load K chunk transposed, V chunk natural
#pragma unroll
        for (int c = 0; c < 4; c++) {
            int idx = t + c * 256;
            int j = idx >> 4;
            int d4 = (idx & 15) * 4;
            float4 kv = *(const float4*)(Kb + (size_t)(jb + j) * 256 + d4);
            Kt[(d4 + 0) * ATT_LD + j] = kv.x;
            Kt[(d4 + 1) * ATT_LD + j] = kv.y;
            Kt[(d4 + 2) * ATT_LD + j] = kv.z;
            Kt[(d4 + 3) * ATT_LD + j] = kv.w;
            float4 vv = *(const float4*)(Vb + (size_t)(jb + j) * 256 + d4);
            *(float4*)&Vs[j * ATT_LD + d4] = vv;
        }
        __syncthreads();

        // S = Q K^T  (each thread: rows ty*4.., cols tx*4..)
        float s[4][4];
#pragma unroll
        for (int r = 0; r < 4; r++)
#pragma unroll
            for (int c = 0; c < 4; c++) s[r][c] = 0.f;
#pragma unroll 8
        for (int k = 0; k < 64; k++) {
            float4 qa = *(const float4*)&Qt[k * ATT_LD + ty * 4];
            float4 kb = *(const float4*)&Kt[k * ATT_LD + tx * 4];
            float ar[4] = {qa.x, qa.y, qa.z, qa.w};
            float br[4] = {kb.x, kb.y, kb.z, kb.w};
#pragma unroll
            for (int r = 0; r < 4; r++)
#pragma unroll
                for (int c = 0; c < 4; c++)
                    s[r][c] = fmaf(ar[r], br[c], s[r][c]);
        }
        // store S transposed: Pt[j][i]
#pragma unroll
        for (int c = 0; c < 4; c++) {
            float4 pv = make_float4(s[0][c], s[1][c], s[2][c], s[3][c]);
            *(float4*)&Pt[(tx * 4 + c) * ATT_LD + ty * 4] = pv;
        }
        __syncthreads();

        // online softmax per row (thread t = row i, t < 64)
        if (t < 64) {
            float mn = m_i;
#pragma unroll 8
            for (int j = 0; j < 64; j++)
                mn = fmaxf(mn, Pt[j * ATT_LD + t] * scale);
            float alpha = __expf(m_i - mn);
            float l = l_i * alpha;
#pragma unroll 8
            for (int j = 0; j < 64; j++) {
                float p = __expf(Pt[j * ATT_LD + t] * scale - mn);
                Pt[j * ATT_LD + t] = p;
                l += p;
            }
            m_i = mn;
            l_i = l;
            sred[t] = alpha;
        }
        __syncthreads();

        // O = O*alpha + P V
        float a0 = sred[ty * 4 + 0], a1 = sred[ty * 4 + 1];
        float a2 = sred[ty * 4 + 2], a3 = sred[ty * 4 + 3];
#pragma unroll
        for (int c = 0; c < 4; c++) {
            o[0][c] *= a0; o[1][c] *= a1; o[2][c] *= a2; o[3][c] *= a3;
        }
#pragma unroll 8
        for (int j = 0; j < 64; j++) {
            float4 pa = *(const float4*)&Pt[j * ATT_LD + ty * 4];
            float4 vb = *(const float4*)&Vs[j * ATT_LD + tx * 4];
            float pr[4] = {pa.x, pa.y, pa.z, pa.w};
            float vr[4] = {vb.x, vb.y, vb.z, vb.w};
#pragma unroll
            for (int r = 0; r < 4; r++)
#pragma unroll
                for (int c = 0; c < 4; c++)
                    o[r][c] = fmaf(pr[r], vr[c], o[r][c]);
        }
    }

    __syncthreads();   // last PV read of sred done before overwrite
    if (t < 64) sred[t] = 1.f / l_i;
    __syncthreads();

#pragma unroll
    for (int r = 0; r < 4; r++) {
        int m = t0 + ty * 4 + r;
        float il = sred[ty * 4 + r];
        float4 ov = make_float4(o[r][0] * il, o[r][1] * il, o[r][2] * il, o[r][3] * il);
        *(float4*)(O + ((size_t)(b * TLEN + m)) * DMODEL + h * 64 + tx * 4) = ov;
    }
}

// ---------------------------------------------------------------------------
// Launch
// ---------------------------------------------------------------------------
extern "C" void kernel_launch(void* const* d_in, const int* in_sizes, int n_in,
                              void* d_out, int out_size)
{
    const float* dec = (const float*)d_in[0];
    const float* enc = (const float*)d_in[1];
    const float* Wq  = (const float*)d_in[2];
    const float* bq  = (const float*)d_in[3];
    const float* Wk  = (const float*)d_in[4];
    const float* bk  = (const float*)d_in[5];
    const float* Wv  = (const float*)d_in[6];
    const float* bv  = (const float*)d_in[7];
    const float* Wo  = (const float*)d_in[8];
    const float* bo  = (const float*)d_in[9];
    float* out = (float*)d_out;

    float *Qb, *Kb, *Vb, *Ab;
    cudaGetSymbolAddress((void**)&Qb, g_Q);
    cudaGetSymbolAddress((void**)&Kb, g_Kc);
    cudaGetSymbolAddress((void**)&Vb, g_Vc);
    cudaGetSymbolAddress((void**)&Ab, g_A);

    cudaFuncSetAttribute(hepos_attn, cudaFuncAttributeMaxDynamicSharedMemorySize,
                         (int)ATT_SMEM);

    dim3 blk(256);
    // 1. Q projection
    hepos_sgemm_nt_bias<<<dim3(8, 32, 1), blk>>>(dec, Wq, bq, Qb, BATCH * TLEN, DMODEL, DMODEL);
    // 2/3. strided K,V projections
    hepos_kv_gemm<<<dim3(2, 32, 16), blk>>>(enc, Wk, bk, Kb);
    hepos_kv_gemm<<<dim3(2, 32, 16), blk>>>(enc, Wv, bv, Vb);
    // 4. attention
    hepos_attn<<<dim3(16, 16, BATCH), blk, ATT_SMEM>>>(Qb, Kb, Vb, Ab);
    // 5. output projection
    hepos_sgemm_nt_bias<<<dim3(8, 32, 1), blk>>>(Ab, Wo, bo, out, BATCH * TLEN, DMODEL, DMODEL);
}

// round 4
// speedup vs baseline: 1.6743x; 1.6743x over previous
#include <cuda_runtime.h>
#include <math.h>
#include <stdint.h>

// ---------------------------------------------------------------------------
// HEPOS cross attention, round 4 (re-run: tf32 change still unmeasured after
// two broker-side container failures; R0 proved the broker fails on the bare
// stub too). tf32 tensor-core GEMMs + fp32 flash attention.
// B=4, T=1024, S=4096, D=1024, 16 heads x 64, head strides [1,2,4,8]*4.
//
// Pipeline (5 kernels, one stream, graph-capturable):
//   1. Q = dec @ Wq^T + bq          (tf32 MMA GEMM-NT, 4096x1024x1024)
//   2. Kc = strided K proj          (tf32 MMA, compacted per stride-group)
//   3. Vc = strided V proj          (tf32 MMA)
//   4. flash attention (fp32)       -> A (B,T,1024)
//   5. out = A @ Wo^T + bo          (tf32 MMA GEMM-NT)
// ---------------------------------------------------------------------------

#define BATCH 4
#define TLEN 1024
#define SLEN 4096
#define DMODEL 1024

__device__ float g_Q[(size_t)BATCH * TLEN * DMODEL];      // 16 MB
__device__ float g_Kc[7864320];                            // 31.5 MB
__device__ float g_Vc[7864320];                            // 31.5 MB
__device__ float g_A[(size_t)BATCH * TLEN * DMODEL];       // 16 MB

__device__ __host__ __forceinline__ size_t grp_off(int g) {
    size_t off = 0;
    if (g > 0) off += 4194304u;   // g0: 4*4096*256
    if (g > 1) off += 2097152u;   // g1: 4*2048*256
    if (g > 2) off += 1048576u;   // g2: 4*1024*256
    return off;
}

__device__ __forceinline__ uint32_t f2tf32(float x) {
    uint32_t r;
    asm("cvt.rna.tf32.f32 %0, %1;" : "=r"(r) : "f"(x));
    return r;
}

#define MMA_TF32(c, a, b0, b1)                                              \
    asm volatile("mma.sync.aligned.m16n8k8.row.col.f32.tf32.tf32.f32 "      \
                 "{%0,%1,%2,%3}, {%4,%5,%6,%7}, {%8,%9}, {%0,%1,%2,%3};"    \
                 : "+f"((c)[0]), "+f"((c)[1]), "+f"((c)[2]), "+f"((c)[3])   \
                 : "r"((a)[0]), "r"((a)[1]), "r"((a)[2]), "r"((a)[3]),      \
                   "r"(b0), "r"(b1))

// ---------------------------------------------------------------------------
// tf32 MMA GEMM-NT with bias: C[M,N] = A[M,K] @ W[N,K]^T + bias[N]
// 128x128 tile, BK=32, 256 threads = 8 warps (4 in M x 2 in N),
// warp tile 32x64 = 2x8 m16n8k8 atoms. Smem [row][k] stride 36 (conflict-free
// fragment loads: bank = 4*(lane/4) + lane%4 = lane).
// ---------------------------------------------------------------------------
#define GLD 36

__global__ __launch_bounds__(256) void hepos_mma_gemm(
    const float* __restrict__ A, const float* __restrict__ W,
    const float* __restrict__ bias, float* __restrict__ C,
    int M, int N, int K)
{
    __shared__ uint32_t As[128][GLD];
    __shared__ uint32_t Bs[128][GLD];

    const int tid = threadIdx.x;
    const int lane = tid & 31;
    const int wid = tid >> 5;
    const int warp_m = wid & 3;      // 4 tiles of 32 rows
    const int warp_n = wid >> 2;     // 2 tiles of 64 cols
    const int lr = lane >> 2;        // 0..7
    const int lc = lane & 3;         // 0..3
    const int m0 = blockIdx.y * 128;
    const int n0 = blockIdx.x * 128;

    const int ldr = tid >> 3;         // 0..31 base row for gmem loads
    const int kq  = (tid & 7) * 4;    // k quad

    const float* Ap = A + (size_t)(m0 + ldr) * K + kq;
    const float* Wp = W + (size_t)(n0 + ldr) * K + kq;

    float acc[2][8][4];
#pragma unroll
    for (int i = 0; i < 2; i++)
#pragma unroll
        for (int j = 0; j < 8; j++)
#pragma unroll
            for (int r = 0; r < 4; r++) acc[i][j][r] = 0.f;

    const int NK = K / 32;

    // prologue: tile 0 -> smem
    {
#pragma unroll
        for (int it = 0; it < 4; it++) {
            float4 av = *(const float4*)(Ap + (size_t)(it * 32) * K);
            float4 wv = *(const float4*)(Wp + (size_t)(it * 32) * K);
            *(uint4*)&As[ldr + it * 32][kq] =
                make_uint4(f2tf32(av.x), f2tf32(av.y), f2tf32(av.z), f2tf32(av.w));
            *(uint4*)&Bs[ldr + it * 32][kq] =
                make_uint4(f2tf32(wv.x), f2tf32(wv.y), f2tf32(wv.z), f2tf32(wv.w));
        }
    }

    for (int kt = 0; kt < NK; kt++) {
        __syncthreads();
        const bool more = (kt + 1 < NK);
        float4 pa[4], pw[4];
        if (more) {
            const int ko = (kt + 1) * 32;
#pragma unroll
            for (int it = 0; it < 4; it++) {
                pa[it] = *(const float4*)(Ap + (size_t)(it * 32) * K + ko);
                pw[it] = *(const float4*)(Wp + (size_t)(it * 32) * K + ko);
            }
        }

#pragma unroll
        for (int ks = 0; ks < 4; ks++) {
            const int kk = ks * 8;
            uint32_t af[2][4];
#pragma unroll
            for (int i = 0; i < 2; i++) {
                int mr = warp_m * 32 + i * 16 + lr;
                af[i][0] = As[mr][kk + lc];
                af[i][1] = As[mr + 8][kk + lc];
                af[i][2] = As[mr][kk + lc + 4];
                af[i][3] = As[mr + 8][kk + lc + 4];
            }
#pragma unroll
            for (int j = 0; j < 8; j++) {
                int nc = warp_n * 64 + j * 8 + lr;
                uint32_t b0 = Bs[nc][kk + lc];
                uint32_t b1 = Bs[nc][kk + lc + 4];
                MMA_TF32(acc[0][j], af[0], b0, b1);
                MMA_TF32(acc[1][j], af[1], b0, b1);
            }
        }
        __syncthreads();
        if (more) {
#pragma unroll
            for (int it = 0; it < 4; it++) {
                *(uint4*)&As[ldr + it * 32][kq] =
                    make_uint4(f2tf32(pa[it].x), f2tf32(pa[it].y),
                               f2tf32(pa[it].z), f2tf32(pa[it].w));
                *(uint4*)&Bs[ldr + it * 32][kq] =
                    make_uint4(f2tf32(pw[it].x), f2tf32(pw[it].y),
                               f2tf32(pw[it].z), f2tf32(pw[it].w));
            }
        }
    }

    // epilogue
#pragma unroll
    for (int i = 0; i < 2; i++) {
        int r0 = m0 + warp_m * 32 + i * 16 + (lane >> 2);
#pragma unroll
        for (int j = 0; j < 8; j++) {
            int cc = n0 + warp_n * 64 + j * 8 + (lane & 3) * 2;
            float2 bv = *(const float2*)(bias + cc);
            float2 o0 = make_float2(acc[i][j][0] + bv.x, acc[i][j][1] + bv.y);
            float2 o1 = make_float2(acc[i][j][2] + bv.x, acc[i][j][3] + bv.y);
            *(float2*)(C + (size_t)r0 * N + cc) = o0;
            *(float2*)(C + (size_t)(r0 + 8) * N + cc) = o1;
        }
    }
}

// ---------------------------------------------------------------------------
// Strided K/V projection per stride-group (tf32 MMA).
//   out[g][b][m][n] = enc[b][m*2^g][:] . W[wrow(n)][:] + bias[wrow(n)]
//   wrow(n) = (g + (n>>6)*4)*64 + (n & 63), n in [0,256)
// Grid: x = n-tile (2), y = m-tile (<=32, early-exit), z = g*4 + b.
// ---------------------------------------------------------------------------
__global__ __launch_bounds__(256) void hepos_mma_kv(
    const float* __restrict__ enc, const float* __restrict__ W,
    const float* __restrict__ bias, float* __restrict__ out)
{
    const int z = blockIdx.z;
    const int g = z >> 2;
    const int b = z & 3;
    const int Mg = SLEN >> g;
    const int m0 = blockIdx.y * 128;
    if (m0 >= Mg) return;
    const int stride = 1 << g;
    const int n0 = blockIdx.x * 128;

    __shared__ uint32_t As[128][GLD];
    __shared__ uint32_t Bs[128][GLD];

    const int tid = threadIdx.x;
    const int lane = tid & 31;
    const int wid = tid >> 5;
    const int warp_m = wid & 3;
    const int warp_n = wid >> 2;
    const int lr = lane >> 2;
    const int lc = lane & 3;

    const int ldr = tid >> 3;
    const int kq  = (tid & 7) * 4;

    const float* Ap = enc + ((size_t)b * SLEN + (size_t)(m0 + ldr) * stride) * DMODEL + kq;

    float acc[2][8][4];
#pragma unroll
    for (int i = 0; i < 2; i++)
#pragma unroll
        for (int j = 0; j < 8; j++)
#pragma unroll
            for (int r = 0; r < 4; r++) acc[i][j][r] = 0.f;

    const int NK = DMODEL / 32;
    const size_t arow_stride = (size_t)stride * DMODEL * 32;  // 32 tile-rows apart

    // W row pointers for the 4 load rows of this thread
    const float* Wp[4];
#pragma unroll
    for (int it = 0; it < 4; it++) {
        int ncol = n0 + ldr + it * 32;
        int wrow = (g + ((ncol >> 6) << 2)) * 64 + (ncol & 63);
        Wp[it] = W + (size_t)wrow * DMODEL + kq;
    }

    {
#pragma unroll
        for (int it = 0; it < 4; it++) {
            float4 av = *(const float4*)(Ap + (size_t)it * arow_stride);
            float4 wv = *(const float4*)(Wp[it]);
            *(uint4*)&As[ldr + it * 32][kq] =
                make_uint4(f2tf32(av.x), f2tf32(av.y), f2tf32(av.z), f2tf32(av.w));
            *(uint4*)&Bs[ldr + it * 32][kq] =
                make_uint4(f2tf32(wv.x), f2tf32(wv.y), f2tf32(wv.z), f2tf32(wv.w));
        }
    }

    for (int kt = 0; kt < NK; kt++) {
        __syncthreads();
        const bool more = (kt + 1 < NK);
        float4 pa[4], pw[4];
        if (more) {
            const int ko = (kt + 1) * 32;
#pragma unroll
            for (int it = 0; it < 4; it++) {
                pa[it] = *(const float4*)(Ap + (size_t)it * arow_stride + ko);
                pw[it] = *(const float4*)(Wp[it] + ko);
            }
        }

#pragma unroll
        for (int ks = 0; ks < 4; ks++) {
            const int kk = ks * 8;
            uint32_t af[2][4];
#pragma unroll
            for (int i = 0; i < 2; i++) {
                int mr = warp_m * 32 + i * 16 + lr;
                af[i][0] = As[mr][kk + lc];
                af[i][1] = As[mr + 8][kk + lc];
                af[i][2] = As[mr][kk + lc + 4];
                af[i][3] = As[mr + 8][kk + lc + 4];
            }
#pragma unroll
            for (int j = 0; j < 8; j++) {
                int nc = warp_n * 64 + j * 8 + lr;
                uint32_t b0 = Bs[nc][kk + lc];
                uint32_t b1 = Bs[nc][kk + lc + 4];
                MMA_TF32(acc[0][j], af[0], b0, b1);
                MMA_TF32(acc[1][j], af[1], b0, b1);
            }
        }
        __syncthreads();
        if (more) {
#pragma unroll
            for (int it = 0; it < 4; it++) {
                *(uint4*)&As[ldr + it * 32][kq] =
                    make_uint4(f2tf32(pa[it].x), f2tf32(pa[it].y),
                               f2tf32(pa[it].z), f2tf32(pa[it].w));
                *(uint4*)&Bs[ldr + it * 32][kq] =
                    make_uint4(f2tf32(pw[it].x), f2tf32(pw[it].y),
                               f2tf32(pw[it].z), f2tf32(pw[it].w));
            }
        }
    }

    const size_t base = grp_off(g) + (size_t)b * Mg * 256;
#pragma unroll
    for (int i = 0; i < 2; i++) {
        int r0 = warp_m * 32 + i * 16 + (lane >> 2) + m0;
#pragma unroll
        for (int j = 0; j < 8; j++) {
            int n = n0 + warp_n * 64 + j * 8 + (lane & 3) * 2;
            int h2 = g + ((n >> 6) << 2);
            float2 bv = *(const float2*)(bias + h2 * 64 + (n & 63));
            float2 o0 = make_float2(acc[i][j][0] + bv.x, acc[i][j][1] + bv.y);
            float2 o1 = make_float2(acc[i][j][2] + bv.x, acc[i][j][3] + bv.y);
            *(float2*)(out + base + (size_t)r0 * 256 + n) = o0;
            *(float2*)(out + base + (size_t)(r0 + 8) * 256 + n) = o1;
        }
    }
}

// ---------------------------------------------------------------------------
// Flash attention over compacted K/V (fp32, parallel softmax).
// Block = (q-tile 64) x head x batch, 256 threads (16x16), 4x4 micro-tiles.
// Q pre-scaled by 1/sqrt(64) at load. Softmax: 4 threads per row, shfl quad
// reductions.
// ---------------------------------------------------------------------------
#define ATT_LD 68
#define ATT_SMEM ((4 * 64 * ATT_LD + 64) * sizeof(float))

__global__ __launch_bounds__(256) void hepos_attn(
    const float* __restrict__ Q, const float* __restrict__ K,
    const float* __restrict__ V, float* __restrict__ O)
{
    extern __shared__ float sm[];
    float* Qt = sm;                        // [d][i]
    float* Kt = Qt + 64 * ATT_LD;          // [d][j]
    float* Pt = Kt + 64 * ATT_LD;          // [j][i]
    float* Vs = Pt + 64 * ATT_LD;          // [j][d]
    float* sred = Vs + 64 * ATT_LD;

    const int t = threadIdx.x;
    const int tx = t & 15, ty = t >> 4;
    const int qt = blockIdx.x;
    const int y = blockIdx.y;
    const int h = ((y & 3) << 2) | (y >> 2);   // heavy (stride-1) heads first
    const int b = blockIdx.z;

    const int g = h & 3;
    const int hig = h >> 2;
    const int Sg = SLEN >> g;
    const float* Kb = K + grp_off(g) + (size_t)b * Sg * 256 + hig * 64;
    const float* Vb = V + grp_off(g) + (size_t)b * Sg * 256 + hig * 64;

    const int t0 = qt * 64;
    const float scale = 0.125f;

    // Q tile transposed + pre-scaled
#pragma unroll
    for (int c = 0; c < 4; c++) {
        int idx = t + c * 256;
        int i = idx >> 4;
        int d4 = (idx & 15) * 4;
        float4 q = *(const float4*)(Q + ((size_t)(b * TLEN + t0 + i)) * DMODEL + h * 64 + d4);
        Qt[(d4 + 0) * ATT_LD + i] = q.x * scale;
        Qt[(d4 + 1) * ATT_LD + i] = q.y * scale;
        Qt[(d4 + 2) * ATT_LD + i] = q.z * scale;
        Qt[(d4 + 3) * ATT_LD + i] = q.w * scale;
    }

    float m_i = -INFINITY, l_i = 0.f;   // replicated across the 4-thread quad
    float o[4][4];
#pragma unroll
    for (int r = 0; r < 4; r++)
#pragma unroll
        for (int c = 0; c < 4; c++) o[r][c] = 0.f;

    const int nch = Sg >> 6;
    const int srow = t >> 2;    // softmax row (0..63)
    const int q4   = t & 3;     // quad lane

    for (int ch = 0; ch < nch; ch++) {
        __syncthreads();
        const int jb = ch * 64;
#pragma unroll
        for (int c = 0; c < 4; c++) {
            int idx = t + c * 256;
            int j = idx >> 4;
            int d4 = (idx & 15) * 4;
            float4 kv = *(const float4*)(Kb + (size_t)(jb + j) * 256 + d4);
            Kt[(d4 + 0) * ATT_LD + j] = kv.x;
            Kt[(d4 + 1) * ATT_LD + j] = kv.y;
            Kt[(d4 + 2) * ATT_LD + j] = kv.z;
            Kt[(d4 + 3) * ATT_LD + j] = kv.w;
            float4 vv = *(const float4*)(Vb + (size_t)(jb + j) * 256 + d4);
            *(float4*)&Vs[j * ATT_LD + d4] = vv;
        }
        __syncthreads();

        // S = (Q*scale) K^T
        float s[4][4];
#pragma unroll
        for (int r = 0; r < 4; r++)
#pragma unroll
            for (int c = 0; c < 4; c++) s[r][c] = 0.f;
#pragma unroll 8
        for (int k = 0; k < 64; k++) {
            float4 qa = *(const float4*)&Qt[k * ATT_LD + ty * 4];
            float4 kb = *(const float4*)&Kt[k * ATT_LD + tx * 4];
            float ar[4] = {qa.x, qa.y, qa.z, qa.w};
            float br[4] = {kb.x, kb.y, kb.z, kb.w};
#pragma unroll
            for (int r = 0; r < 4; r++)
#pragma unroll
                for (int c = 0; c < 4; c++)
                    s[r][c] = fmaf(ar[r], br[c], s[r][c]);
        }
#pragma unroll
        for (int c = 0; c < 4; c++) {
            float4 pv = make_float4(s[0][c], s[1][c], s[2][c], s[3][c]);
            *(float4*)&Pt[(tx * 4 + c) * ATT_LD + ty * 4] = pv;
        }
        __syncthreads();

        // online softmax: 4 threads per row, 16 cols each
        {
            float mloc = -INFINITY;
#pragma unroll
            for (int jj = 0; jj < 16; jj++) {
                int j = q4 + (jj << 2);
                mloc = fmaxf(mloc, Pt[j * ATT_LD + srow]);
            }
            mloc = fmaxf(mloc, __shfl_xor_sync(0xffffffffu, mloc, 1));
            mloc = fmaxf(mloc, __shfl_xor_sync(0xffffffffu, mloc, 2));
            float mn = fmaxf(m_i, mloc);
            float alpha = __expf(m_i - mn);
            float lloc = 0.f;
#pragma unroll
            for (int jj = 0; jj < 16; jj++) {
                int j = q4 + (jj << 2);
                float p = __expf(Pt[j * ATT_LD + srow] - mn);
                Pt[j * ATT_LD + srow] = p;
                lloc += p;
            }
            lloc += __shfl_xor_sync(0xffffffffu, lloc, 1);
            lloc += __shfl_xor_sync(0xffffffffu, lloc, 2);
            l_i = l_i * alpha + lloc;
            m_i = mn;
            if (q4 == 0) sred[srow] = alpha;
        }
        __syncthreads();

        // O = O*alpha + P V
        float a0 = sred[ty * 4 + 0], a1 = sred[ty * 4 + 1];
        float a2 = sred[ty * 4 + 2], a3 = sred[ty * 4 + 3];
#pragma unroll
        for (int c = 0; c < 4; c++) {
            o[0][c] *= a0; o[1][c] *= a1; o[2][c] *= a2; o[3][c] *= a3;
        }
#pragma unroll 8
        for (int j = 0; j < 64; j++) {
            float4 pa = *(const float4*)&Pt[j * ATT_LD + ty * 4];
            float4 vb = *(const float4*)&Vs[j * ATT_LD + tx * 4];
            float pr[4] = {pa.x, pa.y, pa.z, pa.w};
            float vr[4] = {vb.x, vb.y, vb.z, vb.w};
#pragma unroll
            for (int r = 0; r < 4; r++)
#pragma unroll
                for (int c = 0; c < 4; c++)
                    o[r][c] = fmaf(pr[r], vr[c], o[r][c]);
        }
    }

    __syncthreads();
    if (q4 == 0) sred[srow] = 1.f / l_i;
    __syncthreads();

#pragma unroll
    for (int r = 0; r < 4; r++) {
        int m = t0 + ty * 4 + r;
        float il = sred[ty * 4 + r];
        float4 ov = make_float4(o[r][0] * il, o[r][1] * il, o[r][2] * il, o[r][3] * il);
        *(float4*)(O + ((size_t)(b * TLEN + m)) * DMODEL + h * 64 + tx * 4) = ov;
    }
}

// ---------------------------------------------------------------------------
extern "C" void kernel_launch(void* const* d_in, const int* in_sizes, int n_in,
                              void* d_out, int out_size)
{
    const float* dec = (const float*)d_in[0];
    const float* enc = (const float*)d_in[1];
    const float* Wq  = (const float*)d_in[2];
    const float* bq  = (const float*)d_in[3];
    const float* Wk  = (const float*)d_in[4];
    const float* bk  = (const float*)d_in[5];
    const float* Wv  = (const float*)d_in[6];
    const float* bv  = (const float*)d_in[7];
    const float* Wo  = (const float*)d_in[8];
    const float* bo  = (const float*)d_in[9];
    float* out = (float*)d_out;

    float *Qb, *Kb, *Vb, *Ab;
    cudaGetSymbolAddress((void**)&Qb, g_Q);
    cudaGetSymbolAddress((void**)&Kb, g_Kc);
    cudaGetSymbolAddress((void**)&Vb, g_Vc);
    cudaGetSymbolAddress((void**)&Ab, g_A);

    cudaFuncSetAttribute(hepos_attn, cudaFuncAttributeMaxDynamicSharedMemorySize,
                         (int)ATT_SMEM);

    dim3 blk(256);
    hepos_mma_gemm<<<dim3(8, 32, 1), blk>>>(dec, Wq, bq, Qb, BATCH * TLEN, DMODEL, DMODEL);
    hepos_mma_kv<<<dim3(2, 32, 16), blk>>>(enc, Wk, bk, Kb);
    hepos_mma_kv<<<dim3(2, 32, 16), blk>>>(enc, Wv, bv, Vb);
    hepos_attn<<<dim3(16, 16, BATCH), blk, ATT_SMEM>>>(Qb, Kb, Vb, Ab);
    hepos_mma_gemm<<<dim3(8, 32, 1), blk>>>(Ab, Wo, bo, out, BATCH * TLEN, DMODEL, DMODEL);
}